// round 13
// baseline (speedup 1.0000x reference)
#include <cuda_runtime.h>
#include <cstdint>

#define NF    300
#define NF1   299
#define PMAXV 151
#define NTHR  128
#define NW    4     // warps (rows) per CTA
#define CH    10    // elements per lane (30 lanes * 10 = 300)

__device__ __forceinline__ float neg_inf() { return __int_as_float(0xff800000); }

// packed fp32x2 add: one instruction, two independent RN fp32 adds (sm_103a)
__device__ __forceinline__ void addf32x2(unsigned long long& acc, unsigned long long v) {
    asm("add.rn.f32x2 %0, %0, %1;" : "+l"(acc) : "l"(v));
}

__global__ __launch_bounds__(NTHR) void pil_kernel(const float* __restrict__ in,
                                                   float* __restrict__ out, int nrows) {
    const int warp = threadIdx.x >> 5;
    const int lane = threadIdx.x & 31;
    const int row  = blockIdx.x * NW + warp;
    if (row >= nrows) return;                       // warp-uniform exit

    // Per-warp pool: phase 1 = raw[312] floats (raw[i] at [4+i], zero halo);
    // phase 2 = wv[300] float2 (w, w*(i-150)). raw fully consumed into registers
    // before wv is written; __syncwarp() fences the transition. 16B aligned rows.
    __shared__ __align__(16) char s_pool[NW][2432];
    __shared__ int s_pos[NW][PMAXV + 1];

    float*  s_rawp = reinterpret_cast<float*>(s_pool[warp]);
    float2* s_wv   = reinterpret_cast<float2*>(s_pool[warp]);

    // ---- coalesced row load: 75 x float4 ----
    const float4* rowp = reinterpret_cast<const float4*>(in + (size_t)row * NF);
    float4* rw = reinterpret_cast<float4*>(s_rawp);
    for (int idx = lane; idx < 75; idx += 32) rw[idx + 1] = rowp[idx];
    if (lane < 4) { s_rawp[lane] = 0.f; s_rawp[304 + lane] = 0.f; }
    __syncwarp();

    // ---- blur (sigma=2, 7 taps) into registers, contiguous chunk per lane ----
    const float w0 = 0.07015933f, w1 = 0.13107488f, w2 = 0.19071282f, w3 = 0.21610594f;
    const int base = (lane < 30) ? CH * lane : 290;   // lanes 30/31 compute harmless dup
    float r[CH + 6];
    const float* rp = s_rawp + base + 1;              // rp[j] = raw[base-3+j]
    #pragma unroll
    for (int j = 0; j < CH + 6; j++) r[j] = rp[j];
    float b[CH];
    #pragma unroll
    for (int k = 0; k < CH; k++)
        b[k] = w0 * (r[k] + r[k + 6]) + w1 * (r[k + 1] + r[k + 5])
             + w2 * (r[k + 2] + r[k + 4]) + w3 * r[k + 3];
    __syncwarp();   // all lanes done reading raw; pool rewritten as wv below

    // ---- peak detection from registers (strict maxima + boundary rules) ----
    float lft = __shfl_up_sync(0xFFFFFFFFu, b[CH - 1], 1);
    float rgt = __shfl_down_sync(0xFFFFFFFFu, b[0], 1);
    if (lane == 0)  lft = neg_inf();   // element 0: peak iff b0 > b1
    if (lane >= 29) rgt = neg_inf();   // element 299: peak iff b299 > b298
    unsigned pmask = 0;
    if (lane < 30) {
        float prev = lft;
        #pragma unroll
        for (int k = 0; k < CH; k++) {
            float cur = b[k];
            float nxt = (k < CH - 1) ? b[k + 1] : rgt;
            if (cur > prev && cur > nxt) pmask |= (1u << k);
            prev = cur;
        }
    }
    int cnt = __popc(pmask);

    // ---- warp inclusive scan of peak counts -> ordered peak positions ----
    int incl = cnt;
    #pragma unroll
    for (int off = 1; off < 32; off <<= 1) {
        int n = __shfl_up_sync(0xFFFFFFFFu, incl, off);
        if (lane >= off) incl += n;
    }
    const int P = __shfl_sync(0xFFFFFFFFu, incl, 31);
    int k0 = incl - cnt;
    unsigned mm = pmask;
    while (mm) {
        int k = __ffs(mm) - 1;
        s_pos[warp][k0++] = base + k;
        mm &= mm - 1;
    }

    // ---- balanced exp phase: store (w, w*(i-150)) pairs, packed STS.128 ----
    // softargmax is shift-invariant (no max-subtraction; |blur| small).
    if (lane < 30) {
        const float base_c = (float)(base - 150);
        float4* dst = reinterpret_cast<float4*>(s_wv + base);   // base even -> 16B aligned
        #pragma unroll
        for (int k = 0; k < CH; k += 2) {
            float wa = __expf(b[k]);
            float wb = __expf(b[k + 1]);
            dst[k >> 1] = make_float4(wa, wa * (base_c + (float)k),
                                      wb, wb * (base_c + (float)(k + 1)));
        }
    }
    __syncwarp();

    const int nseg = (P > 1) ? P : 1;

    // ---- segment-per-lane: sequential sums via packed f32x2 adds.
    //      One add.rn.f32x2 per element accumulates (den, s1) with rounding
    //      bit-identical to the scalar left-to-right loop (error-correlated
    //      with the reference — hard constraint from R5/R7 failures). ----
    const unsigned long long* s_wv64 = reinterpret_cast<const unsigned long long*>(s_wv);
    float l_sum = 0.f;
    int   l_any = 0;
    float tA = neg_inf(), tB = neg_inf();

    for (int j = lane; j < nseg; j += 32) {
        const int st = j ? ((s_pos[warp][j - 1] + s_pos[warp][j]) >> 1) : 0;
        const int en = (j == nseg - 1) ? NF1 : ((s_pos[warp][j] + s_pos[warp][j + 1]) >> 1);
        unsigned long long acc = 0ull;     // packed (den, s1) = (0.0f, 0.0f)
        int i = st;
        if (i & 1) {                       // align to 16B
            addf32x2(acc, s_wv64[i]); i++;
        }
        const ulonglong2* q = reinterpret_cast<const ulonglong2*>(s_wv64 + i);
        const int np = (en - i) >> 1;
        for (int k = 0; k < np; k++) {
            ulonglong2 v = q[k];           // LDS.128: two packed (w,wc) pairs
            addf32x2(acc, v.x);            // element order preserved
            addf32x2(acc, v.y);
        }
        if ((en - i) & 1) addf32x2(acc, s_wv64[en - 1]);
        float den = __uint_as_float((unsigned)(acc & 0xFFFFFFFFull));
        float s1  = __uint_as_float((unsigned)(acc >> 32));
        float sm = fmaf(0.02f, s1 / den, 0.02f);   // freqs = 0.02*(i-150) + 0.02
        float nq = -sm * sm;
        if (sm > -1.f && sm < 1.f) { l_sum += nq; l_any = 1; }
        if (nq > tA) { tB = tA; tA = nq; }
        else if (nq > tB) { tB = nq; }
    }

    // ---- warp reduction: sum, any, top-2 merge ----
    #pragma unroll
    for (int off = 16; off; off >>= 1) {
        l_sum += __shfl_down_sync(0xFFFFFFFFu, l_sum, off);
        l_any |= __shfl_down_sync(0xFFFFFFFFu, l_any, off);
        float oA = __shfl_down_sync(0xFFFFFFFFu, tA, off);
        float oB = __shfl_down_sync(0xFFFFFFFFu, tB, off);
        if (oA > tA) { tB = fmaxf(tA, oB); tA = oA; }
        else         { tB = fmaxf(tB, oA); }
    }

    if (lane == 0) {
        float res;
        if (l_any) {
            res = l_sum;
        } else {
            float ninf = neg_inf();
            res = ((tA != ninf) ? tA : 0.f) + ((tB != ninf) ? tB : 0.f);
        }
        out[row] = res;   // SCALE = 1
    }
}

extern "C" void kernel_launch(void* const* d_in, const int* in_sizes, int n_in,
                              void* d_out, int out_size) {
    const float* in = (const float*)d_in[0];
    float* out = (float*)d_out;
    const int nrows = in_sizes[0] / NF;
    const int nblk = (nrows + NW - 1) / NW;
    pil_kernel<<<nblk, NTHR>>>(in, out, nrows);
}

// round 14
// speedup vs baseline: 1.2608x; 1.2608x over previous
#include <cuda_runtime.h>

#define NF    300
#define NF1   299
#define PMAXV 151
#define NTHR  128
#define NW    4     // warps (rows) per CTA
#define CH    10    // elements per lane (30 lanes * 10 = 300)

__device__ __forceinline__ float neg_inf() { return __int_as_float(0xff800000); }

__global__ __launch_bounds__(NTHR, 16) void pil_kernel(const float* __restrict__ in,
                                                       float* __restrict__ out, int nrows) {
    const int warp = threadIdx.x >> 5;
    const int lane = threadIdx.x & 31;
    const int row  = blockIdx.x * NW + warp;
    if (row >= nrows) return;                       // warp-uniform exit

    // Per-warp pool: phase 1 = raw[312] floats (raw[i] at [4+i], zero halo);
    // phase 2 = wv[300] float2 (w, w*(i-150)). raw fully consumed into registers
    // before wv is written; __syncwarp() fences the transition. 16B aligned rows.
    __shared__ __align__(16) char s_pool[NW][2432];
    __shared__ int s_pos[NW][PMAXV + 1];

    float*  s_rawp = reinterpret_cast<float*>(s_pool[warp]);
    float2* s_wv   = reinterpret_cast<float2*>(s_pool[warp]);

    // ---- coalesced row load: 75 x float4 ----
    const float4* rowp = reinterpret_cast<const float4*>(in + (size_t)row * NF);
    float4* rw = reinterpret_cast<float4*>(s_rawp);
    for (int idx = lane; idx < 75; idx += 32) rw[idx + 1] = rowp[idx];
    if (lane < 4) { s_rawp[lane] = 0.f; s_rawp[304 + lane] = 0.f; }
    __syncwarp();

    // ---- blur (sigma=2, 7 taps) into registers, contiguous chunk per lane ----
    const float w0 = 0.07015933f, w1 = 0.13107488f, w2 = 0.19071282f, w3 = 0.21610594f;
    const int base = (lane < 30) ? CH * lane : 290;   // lanes 30/31 compute harmless dup
    float r[CH + 6];
    const float* rp = s_rawp + base + 1;              // rp[j] = raw[base-3+j]
    #pragma unroll
    for (int j = 0; j < CH + 6; j++) r[j] = rp[j];
    float b[CH];
    #pragma unroll
    for (int k = 0; k < CH; k++)
        b[k] = w0 * (r[k] + r[k + 6]) + w1 * (r[k + 1] + r[k + 5])
             + w2 * (r[k + 2] + r[k + 4]) + w3 * r[k + 3];
    __syncwarp();   // all lanes done reading raw; pool rewritten as wv below

    // ---- peak detection from registers (strict maxima + boundary rules) ----
    float lft = __shfl_up_sync(0xFFFFFFFFu, b[CH - 1], 1);
    float rgt = __shfl_down_sync(0xFFFFFFFFu, b[0], 1);
    if (lane == 0)  lft = neg_inf();   // element 0: peak iff b0 > b1
    if (lane >= 29) rgt = neg_inf();   // element 299: peak iff b299 > b298
    unsigned pmask = 0;
    if (lane < 30) {
        float prev = lft;
        #pragma unroll
        for (int k = 0; k < CH; k++) {
            float cur = b[k];
            float nxt = (k < CH - 1) ? b[k + 1] : rgt;
            if (cur > prev && cur > nxt) pmask |= (1u << k);
            prev = cur;
        }
    }
    int cnt = __popc(pmask);

    // ---- warp inclusive scan of peak counts -> ordered peak positions ----
    int incl = cnt;
    #pragma unroll
    for (int off = 1; off < 32; off <<= 1) {
        int n = __shfl_up_sync(0xFFFFFFFFu, incl, off);
        if (lane >= off) incl += n;
    }
    const int P = __shfl_sync(0xFFFFFFFFu, incl, 31);
    int k0 = incl - cnt;
    unsigned mm = pmask;
    while (mm) {
        int k = __ffs(mm) - 1;
        s_pos[warp][k0++] = base + k;
        mm &= mm - 1;
    }

    // ---- balanced exp phase: store (w, w*(i-150)) pairs, packed STS.128 ----
    // softargmax is shift-invariant (no max-subtraction; |blur| small).
    if (lane < 30) {
        const float base_c = (float)(base - 150);
        float4* dst = reinterpret_cast<float4*>(s_wv + base);   // base even -> 16B aligned
        #pragma unroll
        for (int k = 0; k < CH; k += 2) {
            float wa = __expf(b[k]);
            float wb = __expf(b[k + 1]);
            dst[k >> 1] = make_float4(wa, wa * (base_c + (float)k),
                                      wb, wb * (base_c + (float)(k + 1)));
        }
    }
    __syncwarp();

    const int nseg = (P > 1) ? P : 1;

    // ---- segment-per-lane: sequential fp32 sums (error-correlated w/ ref),
    //      float4-vectorized loads with identical rounding order ----
    float l_sum = 0.f;
    int   l_any = 0;
    float tA = neg_inf(), tB = neg_inf();

    for (int j = lane; j < nseg; j += 32) {
        const int st = j ? ((s_pos[warp][j - 1] + s_pos[warp][j]) >> 1) : 0;
        const int en = (j == nseg - 1) ? NF1 : ((s_pos[warp][j] + s_pos[warp][j + 1]) >> 1);
        float den = 0.f, s1 = 0.f;
        int i = st;
        if (i & 1) {                       // align to float4
            float2 v = s_wv[i];
            den += v.x; s1 += v.y; i++;
        }
        const float4* q = reinterpret_cast<const float4*>(s_wv + i);
        const int np = (en - i) >> 1;
        for (int k = 0; k < np; k++) {
            float4 v = q[k];
            den += v.x; s1 += v.y;         // element order preserved ->
            den += v.z; s1 += v.w;         // rounding identical to scalar loop
        }
        if ((en - i) & 1) {
            float2 v = s_wv[en - 1];
            den += v.x; s1 += v.y;
        }
        float sm = fmaf(0.02f, s1 / den, 0.02f);   // freqs = 0.02*(i-150) + 0.02
        float nq = -sm * sm;
        if (sm > -1.f && sm < 1.f) { l_sum += nq; l_any = 1; }
        if (nq > tA) { tB = tA; tA = nq; }
        else if (nq > tB) { tB = nq; }
    }

    // ---- warp reduction: sum, any, top-2 merge ----
    #pragma unroll
    for (int off = 16; off; off >>= 1) {
        l_sum += __shfl_down_sync(0xFFFFFFFFu, l_sum, off);
        l_any |= __shfl_down_sync(0xFFFFFFFFu, l_any, off);
        float oA = __shfl_down_sync(0xFFFFFFFFu, tA, off);
        float oB = __shfl_down_sync(0xFFFFFFFFu, tB, off);
        if (oA > tA) { tB = fmaxf(tA, oB); tA = oA; }
        else         { tB = fmaxf(tB, oA); }
    }

    if (lane == 0) {
        float res;
        if (l_any) {
            res = l_sum;
        } else {
            float ninf = neg_inf();
            res = ((tA != ninf) ? tA : 0.f) + ((tB != ninf) ? tB : 0.f);
        }
        out[row] = res;   // SCALE = 1
    }
}

extern "C" void kernel_launch(void* const* d_in, const int* in_sizes, int n_in,
                              void* d_out, int out_size) {
    const float* in = (const float*)d_in[0];
    float* out = (float*)d_out;
    const int nrows = in_sizes[0] / NF;
    const int nblk = (nrows + NW - 1) / NW;
    pil_kernel<<<nblk, NTHR>>>(in, out, nrows);
}